// round 13
// baseline (speedup 1.0000x reference)
#include <cuda_runtime.h>
#include <cstdint>

// CVXPolicy_Integrator, round 13: round-12 pipeline with correctness fixes.
// - one commit per station (empty commits at stations 4,5) so CP_WAIT(1)
//   always guarantees the chunk converted this station has landed
// - no smem aliasing: r2 reduction via atomicAdd into dedicated r2acc[128]
// 3-slot zf(f32)/xs(fp16) rings; chunks 0',1' of next tile converted inside
// the GEMM2 region; tanh via MUFU rcp.

#define Bq 131072
#define Dq 256
#define Hq 100
#define GRID 148
#define NT 512
#define NTILES (Bq / 128)

#define W1SW 136           // w1t row stride u32 (136%32==8)
#define XSW  24            // xs row stride u32 (24%32==24)
#define XBUF (128 * XSW)   // 3072 u32 per fp16 chunk slot
#define HPU  56            // h row width in u32 (112 halves)

// ---- smem u32 offsets ----
#define OFF_W1  0                          // 104*136 = 14144
#define OFF_W2  (OFF_W1 + 104 * W1SW)      // +14336
#define OFF_ZF  (OFF_W2 + 256 * HPU)       // +3*4096  f32 chunk ring
#define OFF_XS  (OFF_ZF + 3 * 4096)        // +3*3072  fp16 chunk ring
#define OFF_HS  (OFF_XS + 3 * XBUF)        // +7168
#define OFF_F32 (OFF_HS + 128 * HPU)
// f32 region: w1r0[104] b1s[104] b2s[256] tss[128] r2acc[128] scs[128]
#define SMEMT ((OFF_F32 + 104 + 104 + 256 + 128 + 128 + 128) * 4)  // 232000 B

// ---------------- helpers ----------------
__device__ __forceinline__ unsigned pack_h2(float lo, float hi) {
    unsigned u;
    asm("cvt.rn.f16x2.f32 %0, %1, %2;" : "=r"(u) : "f"(hi), "f"(lo));
    return u;
}
__device__ __forceinline__ void mma_f16(float* c,
                                        unsigned a0, unsigned a1, unsigned a2, unsigned a3,
                                        unsigned b0, unsigned b1) {
    asm volatile(
        "mma.sync.aligned.m16n8k16.row.col.f32.f16.f16.f32 "
        "{%0,%1,%2,%3}, {%4,%5,%6,%7}, {%8,%9}, {%0,%1,%2,%3};"
        : "+f"(c[0]), "+f"(c[1]), "+f"(c[2]), "+f"(c[3])
        : "r"(a0), "r"(a1), "r"(a2), "r"(a3), "r"(b0), "r"(b1));
}
__device__ __forceinline__ void cp_async16(void* sdst, const void* gsrc) {
    unsigned s = (unsigned)__cvta_generic_to_shared(sdst);
    asm volatile("cp.async.cg.shared.global [%0], [%1], 16;" :: "r"(s), "l"(gsrc));
}
#define CP_COMMIT() asm volatile("cp.async.commit_group;")
#define CP_WAIT(n)  asm volatile("cp.async.wait_group %0;" :: "n"(n))

__device__ __forceinline__ int permu(int u) {
    return (u & ~7) | ((u & 3) << 1) | ((u >> 2) & 1);
}

union F2U { float2 f; unsigned long long u; };
__device__ __forceinline__ float2 add2(float2 a, float2 b) {
    F2U A, B, C; A.f = a; B.f = b;
    asm("add.rn.f32x2 %0, %1, %2;" : "=l"(C.u) : "l"(A.u), "l"(B.u));
    return C.f;
}
__device__ __forceinline__ float2 fma2(float2 a, float2 b, float2 c) {
    F2U A, B, C, D; A.f = a; B.f = b; C.f = c;
    asm("fma.rn.f32x2 %0, %1, %2, %3;" : "=l"(D.u) : "l"(A.u), "l"(B.u), "l"(C.u));
    return D.f;
}
__device__ __forceinline__ float2 mul2(float2 a, float2 b) {
    F2U A, B, C; A.f = a; B.f = b;
    asm("mul.rn.f32x2 %0, %1, %2;" : "=l"(C.u) : "l"(A.u), "l"(B.u));
    return C.f;
}

// tanh via MUFU rcp: |err| ~1e-7 rel (invisible under fp16 4e-4)
__device__ __forceinline__ float tanh_fast(float x) {
    float ax = fabsf(x);
    float e  = __expf(-2.0f * ax);
    float th = 1.0f - __fdividef(2.0f * e, 1.0f + e);
    return copysignf(th, x);
}

__global__ void __launch_bounds__(NT, 1)
fused_policy(const float* __restrict__ z, const float* __restrict__ t,
             const float* __restrict__ W1, const float* __restrict__ b1,
             const float* __restrict__ W2, const float* __restrict__ b2,
             float* __restrict__ out)
{
    extern __shared__ unsigned sm[];
    unsigned* w1t = sm + OFF_W1;
    unsigned* w2t = sm + OFF_W2;
    unsigned* zf  = sm + OFF_ZF;
    unsigned* xs  = sm + OFF_XS;
    unsigned* hs  = sm + OFF_HS;
    float* w1r0  = (float*)(sm + OFF_F32);
    float* b1s   = w1r0 + 104;
    float* b2s   = b1s + 104;
    float* tss   = b2s + 256;
    float* r2acc = tss + 128;
    float* scs   = r2acc + 128;

    const int tid = threadIdx.x;

    // ---- one-time weights ----
    for (int idx = tid; idx < 128 * 104; idx += NT) {
        int u = idx / 104, n = idx - u * 104;
        float f0 = 0.f, f1 = 0.f;
        if (n < Hq) {
            f0 = W1[(2 * u + 1) * Hq + n];
            f1 = W1[(2 * u + 2) * Hq + n];
        }
        w1t[n * W1SW + permu(u)] = pack_h2(f0, f1);
    }
    for (int idx = tid; idx < HPU * Dq; idx += NT) {
        int u = idx >> 8, n = idx & 255;
        int k0 = 2 * u;
        float f0 = (k0 < Hq) ? W2[k0 * Dq + n] : 0.f;
        float f1 = (k0 + 1 < Hq) ? W2[(k0 + 1) * Dq + n] : 0.f;
        w2t[n * HPU + permu(u)] = pack_h2(f0, f1);
    }
    if (tid < 104) {
        w1r0[tid] = (tid < Hq) ? W1[tid] : 0.f;
        b1s[tid]  = (tid < Hq) ? b1[tid] : 0.f;
    }
    if (tid < Dq) b2s[tid] = b2[tid];
    if (tid < 128) r2acc[tid] = 0.f;
    for (int idx = tid; idx < 128 * HPU; idx += NT) hs[idx] = 0u;

    const int warp = tid >> 5, lane = tid & 31;
    const int gid = lane >> 2, tig = lane & 3;
    const int m0  = (warp & 3) * 32;
    const int ng  = warp >> 2;
    const int tb  = ng ? (1 + 3 * ng) : 0;     // {0,4,7,10}
    const int ntc = ng ? 3 : 4;                // {4,3,3,3}
    const int n0  = ng * 64;
    const int mr  = m0 + gid;

    // ---- pipeline counters (all FIFO: issue -> convert(+2 stations) -> mma) ----
    int pt = blockIdx.x, pc = 0, pb = 0;   // issue: chunk -> zf[pb]
    int cb = 0;                            // convert: zf[cb] -> xs[cb]
    int mb = 0;                            // consume: xs[mb]

    #define ZISSUE() do {                                                        \
        if (pt < NTILES) {                                                       \
            const float4* srcb = (const float4*)z + ((size_t)pt * 128) * 64 + pc * 8; \
            float4* dst = (float4*)(zf + pb * 4096);                             \
            int r0_ = tid >> 3, c4_ = tid & 7;                                   \
            cp_async16(dst + tid,       srcb + (size_t)r0_ * 64 + c4_);          \
            cp_async16(dst + tid + 512, srcb + (size_t)(r0_ + 64) * 64 + c4_);   \
        }                                                                        \
        CP_COMMIT();                                                             \
        pc++; if (pc == 8) { pc = 0; pt += GRID; }                               \
        pb++; if (pb == 3) pb = 0;                                               \
    } while (0)

    #define ZCONV() do {                                                        \
        const float4* s4 = (const float4*)(zf + cb * 4096);                      \
        unsigned* dx = xs + cb * XBUF;                                           \
        _Pragma("unroll")                                                        \
        for (int j = 0; j < 2; j++) {                                            \
            int q = tid + j * 512;                                               \
            int r = q >> 3, c4 = q & 7;                                          \
            float4 v = s4[q];                                                    \
            int pos0 = ((c4 & 1) << 2) | ((c4 >> 1) & 1) | ((c4 & 4) << 1);      \
            unsigned* dd = dx + r * XSW;                                         \
            dd[pos0]     = pack_h2(v.x, v.y);                                    \
            dd[pos0 + 2] = pack_h2(v.z, v.w);                                    \
        }                                                                        \
        cb++; if (cb == 3) cb = 0;                                               \
    } while (0)

    float acc[4][2][4];
    #pragma unroll
    for (int nt = 0; nt < 4; nt++)
        #pragma unroll
        for (int mf = 0; mf < 2; mf++)
            #pragma unroll
            for (int i = 0; i < 4; i++) acc[nt][mf][i] = 0.0f;

    #define MMA1(sc) do {                                                        \
        const unsigned* xa = xs + mb * XBUF + mr * XSW + 2 * tig;                \
        const unsigned* wb = w1t + (tb * 8 + gid) * W1SW + (sc) * 16 + 2 * tig;  \
        _Pragma("unroll")                                                        \
        for (int ks = 0; ks < 2; ks++) {                                         \
            const int u0 = ks * 8;                                               \
            uint2 A0 = *(const uint2*)(xa + u0);                                 \
            uint2 A1 = *(const uint2*)(xa + 8 * XSW + u0);                       \
            uint2 A2 = *(const uint2*)(xa + 16 * XSW + u0);                      \
            uint2 A3 = *(const uint2*)(xa + 24 * XSW + u0);                      \
            _Pragma("unroll")                                                    \
            for (int nt = 0; nt < 4; nt++) {                                     \
                if (nt < ntc) {                                                  \
                    uint2 bb = *(const uint2*)(wb + nt * 8 * W1SW + u0);         \
                    mma_f16(acc[nt][0], A0.x, A1.x, A0.y, A1.y, bb.x, bb.y);     \
                    mma_f16(acc[nt][1], A2.x, A3.x, A2.y, A3.y, bb.x, bb.y);     \
                }                                                                \
            }                                                                    \
        }                                                                        \
        mb++; if (mb == 3) mb = 0;                                               \
    } while (0)

    // ---- prologue: issue 0,1,2,3; convert 0,1 ----
    ZISSUE(); ZISSUE();                 // chunks 0,1
    CP_WAIT(1); __syncthreads();        // chunk 0 landed + weights/zeros visible
    ZISSUE();                           // chunk 2
    ZCONV();                            // chunk 0 -> xs[0]
    CP_WAIT(1); __syncthreads();        // chunk 1 landed
    ZISSUE();                           // chunk 3
    ZCONV();                            // chunk 1 -> xs[1]

    for (int tile = blockIdx.x; tile < NTILES; tile += GRID) {
        if (tid < 128) tss[tid] = t[tile * 128 + tid];

        // ---- GEMM1 stations s=0..7 (one commit per station) ----
        #pragma unroll
        for (int s = 0; s < 8; s++) {
            if (s <= 5) CP_WAIT(1);           // group from 2 stations ago landed
            __syncthreads();
            if (s <= 3 || s >= 6) ZISSUE();   // chunks s+4, then 0',1'
            else CP_COMMIT();                 // empty group keeps accounting uniform
            if (s <= 5) ZCONV();              // chunk s+2
            MMA1(s);
        }

        // ---- epilogue1: bias + t*W1row0 + tanh -> hs ----
        {
            const float tA0 = tss[mr],      tB0 = tss[mr + 8];
            const float tA1 = tss[mr + 16], tB1 = tss[mr + 24];
            #pragma unroll
            for (int nt = 0; nt < 4; nt++) {
                if (nt < ntc) {
                    int u = (tb + nt) * 4 + tig;
                    int col = 2 * u;
                    int pos = permu(u);
                    float bb0 = b1s[col], bb1 = b1s[col + 1];
                    float w0 = w1r0[col], w1v = w1r0[col + 1];
                    hs[mr * HPU + pos] = pack_h2(
                        tanh_fast(fmaf(tA0, w0, acc[nt][0][0] + bb0)),
                        tanh_fast(fmaf(tA0, w1v, acc[nt][0][1] + bb1)));
                    hs[(mr + 8) * HPU + pos] = pack_h2(
                        tanh_fast(fmaf(tB0, w0, acc[nt][0][2] + bb0)),
                        tanh_fast(fmaf(tB0, w1v, acc[nt][0][3] + bb1)));
                    hs[(mr + 16) * HPU + pos] = pack_h2(
                        tanh_fast(fmaf(tA1, w0, acc[nt][1][0] + bb0)),
                        tanh_fast(fmaf(tA1, w1v, acc[nt][1][1] + bb1)));
                    hs[(mr + 24) * HPU + pos] = pack_h2(
                        tanh_fast(fmaf(tB1, w0, acc[nt][1][2] + bb0)),
                        tanh_fast(fmaf(tB1, w1v, acc[nt][1][3] + bb1)));
                    #pragma unroll
                    for (int mf = 0; mf < 2; mf++)
                        acc[nt][mf][0] = acc[nt][mf][1] = acc[nt][mf][2] = acc[nt][mf][3] = 0.0f;
                }
            }
        }

        // ---- GEMM2 with interleaved next-tile conversions (stations 8,9) ----
        float a2c[8][2][4];
        #pragma unroll
        for (int nt = 0; nt < 8; nt++)
            #pragma unroll
            for (int mf = 0; mf < 2; mf++)
                #pragma unroll
                for (int i = 0; i < 4; i++) a2c[nt][mf][i] = 0.0f;

        CP_WAIT(1); __syncthreads();    // hs visible + chunk 0' landed
        ZISSUE();                       // chunk 2'
        ZCONV();                        // chunk 0'

        const unsigned* ha = hs + mr * HPU + 2 * tig;
        const unsigned* wb2 = w2t + (n0 + gid) * HPU + 2 * tig;

        #pragma unroll
        for (int ks = 0; ks < 4; ks++) {
            const int u0 = ks * 8;
            uint2 A0 = *(const uint2*)(ha + u0);
            uint2 A1 = *(const uint2*)(ha + 8 * HPU + u0);
            uint2 A2 = *(const uint2*)(ha + 16 * HPU + u0);
            uint2 A3 = *(const uint2*)(ha + 24 * HPU + u0);
            #pragma unroll
            for (int nt = 0; nt < 8; nt++) {
                uint2 bb = *(const uint2*)(wb2 + nt * 8 * HPU + u0);
                mma_f16(a2c[nt][0], A0.x, A1.x, A0.y, A1.y, bb.x, bb.y);
                mma_f16(a2c[nt][1], A2.x, A3.x, A2.y, A3.y, bb.x, bb.y);
            }
        }

        CP_WAIT(1); __syncthreads();    // chunk 1' landed
        ZISSUE();                       // chunk 3'
        ZCONV();                        // chunk 1'

        #pragma unroll
        for (int ks = 4; ks < 7; ks++) {
            const int u0 = ks * 8;
            uint2 A0 = *(const uint2*)(ha + u0);
            uint2 A1 = *(const uint2*)(ha + 8 * HPU + u0);
            uint2 A2 = *(const uint2*)(ha + 16 * HPU + u0);
            uint2 A3 = *(const uint2*)(ha + 24 * HPU + u0);
            #pragma unroll
            for (int nt = 0; nt < 8; nt++) {
                uint2 bb = *(const uint2*)(wb2 + nt * 8 * HPU + u0);
                mma_f16(a2c[nt][0], A0.x, A1.x, A0.y, A1.y, bb.x, bb.y);
                mma_f16(a2c[nt][1], A2.x, A3.x, A2.y, A3.y, bb.x, bb.y);
            }
        }

        // ---- epilogue2: bias + r2 (atomic accumulate) + Lambert + store ----
        float2 S0 = make_float2(0.f, 0.f), S1 = S0, S2 = S0, S3 = S0;
        #pragma unroll
        for (int nt = 0; nt < 8; nt++) {
            int col = n0 + nt * 8 + 2 * tig;
            float2 b01 = *(const float2*)&b2s[col];
            float2 v0 = add2(make_float2(a2c[nt][0][0], a2c[nt][0][1]), b01);
            float2 v1 = add2(make_float2(a2c[nt][0][2], a2c[nt][0][3]), b01);
            float2 v2 = add2(make_float2(a2c[nt][1][0], a2c[nt][1][1]), b01);
            float2 v3 = add2(make_float2(a2c[nt][1][2], a2c[nt][1][3]), b01);
            S0 = fma2(v0, v0, S0);
            S1 = fma2(v1, v1, S1);
            S2 = fma2(v2, v2, S2);
            S3 = fma2(v3, v3, S3);
            a2c[nt][0][0] = v0.x; a2c[nt][0][1] = v0.y;
            a2c[nt][0][2] = v1.x; a2c[nt][0][3] = v1.y;
            a2c[nt][1][0] = v2.x; a2c[nt][1][1] = v2.y;
            a2c[nt][1][2] = v3.x; a2c[nt][1][3] = v3.y;
        }
        float s0 = S0.x + S0.y, s1 = S1.x + S1.y;
        float s2 = S2.x + S2.y, s3 = S3.x + S3.y;
        s0 += __shfl_xor_sync(0xffffffffu, s0, 1); s0 += __shfl_xor_sync(0xffffffffu, s0, 2);
        s1 += __shfl_xor_sync(0xffffffffu, s1, 1); s1 += __shfl_xor_sync(0xffffffffu, s1, 2);
        s2 += __shfl_xor_sync(0xffffffffu, s2, 1); s2 += __shfl_xor_sync(0xffffffffu, s2, 2);
        s3 += __shfl_xor_sync(0xffffffffu, s3, 1); s3 += __shfl_xor_sync(0xffffffffu, s3, 2);
        if (tig == 0) {
            atomicAdd(&r2acc[mr],      s0);
            atomicAdd(&r2acc[mr + 8],  s1);
            atomicAdd(&r2acc[mr + 16], s2);
            atomicAdd(&r2acc[mr + 24], s3);
        }
        __syncthreads();

        if (tid < 128) {
            float rr2 = r2acc[tid];
            r2acc[tid] = 0.f;               // ready for next tile (bars before reuse)
            float w = log1pf(rr2);
            #pragma unroll
            for (int it = 0; it < 10; it++) {
                float ew  = __expf(w);
                float num = fmaf(w, ew, -rr2);
                float den = fmaf(w, ew, ew);
                w = w - __fdividef(num, den);
            }
            w = fmaxf(w, 0.0f);
            float tn = sqrtf(w);
            float rr = sqrtf(rr2);
            float scale = (rr > 1e-12f) ? __fdividef(tn, fmaxf(rr, 1e-12f)) : 1.0f;
            scs[tid] = -scale;
        }
        __syncthreads();

        const float2 sc0 = make_float2(scs[mr], scs[mr]);
        const float2 sc1 = make_float2(scs[mr + 8], scs[mr + 8]);
        const float2 sc2 = make_float2(scs[mr + 16], scs[mr + 16]);
        const float2 sc3 = make_float2(scs[mr + 24], scs[mr + 24]);
        const size_t rb = ((size_t)tile * 128 + mr) * Dq;
        #pragma unroll
        for (int nt = 0; nt < 8; nt++) {
            int col = n0 + nt * 8 + 2 * tig;
            *(float2*)&out[rb + col]           = mul2(sc0, make_float2(a2c[nt][0][0], a2c[nt][0][1]));
            *(float2*)&out[rb + 8  * Dq + col] = mul2(sc1, make_float2(a2c[nt][0][2], a2c[nt][0][3]));
            *(float2*)&out[rb + 16 * Dq + col] = mul2(sc2, make_float2(a2c[nt][1][0], a2c[nt][1][1]));
            *(float2*)&out[rb + 24 * Dq + col] = mul2(sc3, make_float2(a2c[nt][1][2], a2c[nt][1][3]));
        }
    }
}

// ---------------- launch ----------------
extern "C" void kernel_launch(void* const* d_in, const int* in_sizes, int n_in,
                              void* d_out, int out_size)
{
    const float* z  = (const float*)d_in[0];
    const float* t  = (const float*)d_in[1];
    const float* W1 = (const float*)d_in[2];
    const float* b1 = (const float*)d_in[3];
    const float* W2 = (const float*)d_in[4];
    const float* b2 = (const float*)d_in[5];
    float* out = (float*)d_out;

    cudaFuncSetAttribute(fused_policy, cudaFuncAttributeMaxDynamicSharedMemorySize, SMEMT);
    fused_policy<<<GRID, NT, SMEMT>>>(z, t, W1, b1, W2, b2, out);
}